// round 2
// baseline (speedup 1.0000x reference)
#include <cuda_runtime.h>
#include <math.h>

// ---------------- problem constants ----------------
#define FFTN     512
#define HOPW     128
#define PADW     256
#define NFREQ    257           // rfft bins
#define NBANDS   80
#define BATCH    32
#define LCONST   320000
#define NFRAMES  2000          // magnitude frames
#define TFR      2501          // STFT frames  (L/HOP + 1)
#define LPAD     (LCONST + 2*PADW)   // 320512

// ---------------- device scratch (static, no runtime alloc) ----------------
__device__ float        g_ola[(size_t)BATCH * LPAD];   // ~41 MB overlap-add accumulator
__device__ float        g_window[FFTN];
__device__ float2       g_tw[FFTN/2];                  // exp(-2*pi*i*j/512), j=0..255
__device__ int          g_band[NFREQ];                 // bin -> mel band (or -1)
__device__ float        g_denom[LPAD];                 // window^2 OLA denominator
__device__ unsigned int g_maxbits[BATCH];              // per-batch max |y| (float bits)

// ---------------- init: tables ----------------
__global__ void k_init() {
    int i = threadIdx.x;   // 512 threads, 1 block
    // periodic hann window (double precision -> f32)
    double ang = 2.0 * 3.14159265358979323846 * (double)i / (double)FFTN;
    g_window[i] = (float)(0.5 * (1.0 - cos(ang)));
    if (i < FFTN/2) {
        double a = -2.0 * 3.14159265358979323846 * (double)i / (double)FFTN;
        g_tw[i] = make_float2((float)cos(a), (float)sin(a));
    }
    if (i < NFREQ) {
        // replicate numpy: mel linspace (f64), hz, edges = (hz/8000).astype(f32)
        double mel_max = 2595.0 * log10(1.0 + 8000.0 / 700.0);
        double step = mel_max / (double)NBANDS;
        float freq = (float)i / 256.0f;   // linspace(0,1,257): exact i/256
        int cnt = 0;
        for (int j = 0; j <= NBANDS; j++) {
            double mel = (j == NBANDS) ? mel_max : (double)j * step;
            double hz  = 700.0 * (pow(10.0, mel / 2595.0) - 1.0);
            float  e   = (float)(hz / 8000.0);
            if (e <= freq) cnt++;   // searchsorted(..., side='right')
        }
        int band = cnt - 1;
        g_band[i] = (band >= 0 && band < NBANDS) ? band : -1;
    }
    if (i < BATCH) g_maxbits[i] = 0u;
}

// ---------------- prep: zero OLA scratch + window^2 denominator ----------------
__global__ void k_prep() {
    int stride = gridDim.x * blockDim.x;
    int idx = blockIdx.x * blockDim.x + threadIdx.x;
    for (size_t i = idx; i < (size_t)BATCH * LPAD; i += stride)
        g_ola[i] = 0.0f;
    for (int p = idx; p < LPAD; p += stride) {
        float wsq = 0.0f;
        int tmax = p >> 7;   // p / HOP
        #pragma unroll
        for (int dt = 0; dt < 4; dt++) {
            int t = tmax - dt;
            if (t >= 0 && t < TFR) {
                int o = p - t * HOPW;   // always in [0,512)
                float w = g_window[o];
                wsq += w * w;
            }
        }
        g_denom[p] = (wsq > 1e-11f) ? wsq : 1.0f;
    }
}

// ---------------- per-frame STFT -> mask -> ISTFT -> OLA ----------------
__global__ void __launch_bounds__(256)
k_frames(const float* __restrict__ mag, const float* __restrict__ noise) {
    __shared__ float2 sA[FFTN];
    __shared__ float2 sB[FFTN];
    __shared__ float  s_win[FFTN];
    __shared__ float2 s_tw[FFTN/2];
    __shared__ float  smask[NFREQ];

    const int t   = blockIdx.x;
    const int b   = blockIdx.y;
    const int tid = threadIdx.x;

    // stage tables into shared
    s_tw[tid] = g_tw[tid];
    s_win[tid]       = g_window[tid];
    s_win[tid + 256] = g_window[tid + 256];

    // interpolated mel-band mask for this frame (all 257 bins — strided so
    // bin 256 (Nyquist) is covered by a 256-thread block)
    for (int f = tid; f < NFREQ; f += 256) {
        int band = g_band[f];
        float m = 0.0f;
        if (band >= 0) {
            double pos = (double)t * ((double)(NFRAMES - 1) / (double)(TFR - 1));
            int i0 = (int)pos;
            int i1 = (i0 + 1 < NFRAMES) ? (i0 + 1) : (NFRAMES - 1);
            float w = (float)(pos - (double)i0);
            const float* row = mag + ((size_t)b * NBANDS + band) * NFRAMES;
            m = row[i0] * (1.0f - w) + row[i1] * w;
        }
        smask[f] = m;
    }
    __syncthreads();

    // load windowed frame with reflect padding
    const int base = t * HOPW;
    const size_t noff = (size_t)b * LCONST;
    #pragma unroll
    for (int h = 0; h < 2; h++) {
        int j = tid + h * 256;
        int q = base + j - PADW;
        if (q < 0)        q = -q;
        if (q >= LCONST)  q = 2 * (LCONST - 1) - q;
        sA[j] = make_float2(noise[noff + q] * s_win[j], 0.0f);
    }
    __syncthreads();

    float2* src = sA;
    float2* dst = sB;

    // ---- forward 512-pt complex FFT (Stockham autosort, 9 radix-2 stages) ----
    #pragma unroll
    for (int s = 0; s < 9; s++) {
        int l   = 1 << s;
        int k   = tid & (l - 1);
        int blk = tid >> s;
        float2 w = s_tw[k << (8 - s)];
        float2 u  = src[tid];
        float2 v0 = src[tid + 256];
        float2 v  = make_float2(w.x * v0.x - w.y * v0.y, w.x * v0.y + w.y * v0.x);
        int o = (blk << (s + 1)) + k;
        dst[o]     = make_float2(u.x + v.x, u.y + v.y);
        dst[o + l] = make_float2(u.x - v.x, u.y - v.y);
        __syncthreads();
        float2* tmp = src; src = dst; dst = tmp;
    }

    // ---- apply real mask with Hermitian mirroring ----
    {
        float m0 = smask[tid];
        float m1 = smask[(tid == 0) ? 256 : (256 - tid)];
        float2 a = src[tid];       a.x *= m0; a.y *= m0; src[tid]       = a;
        float2 c = src[tid + 256]; c.x *= m1; c.y *= m1; src[tid + 256] = c;
    }
    __syncthreads();

    // ---- inverse FFT (conjugate twiddles), scale 1/N applied at the end ----
    #pragma unroll
    for (int s = 0; s < 9; s++) {
        int l   = 1 << s;
        int k   = tid & (l - 1);
        int blk = tid >> s;
        float2 w = s_tw[k << (8 - s)];
        w.y = -w.y;
        float2 u  = src[tid];
        float2 v0 = src[tid + 256];
        float2 v  = make_float2(w.x * v0.x - w.y * v0.y, w.x * v0.y + w.y * v0.x);
        int o = (blk << (s + 1)) + k;
        dst[o]     = make_float2(u.x + v.x, u.y + v.y);
        dst[o + l] = make_float2(u.x - v.x, u.y - v.y);
        __syncthreads();
        float2* tmp = src; src = dst; dst = tmp;
    }

    // ---- window + overlap-add ----
    const float scale = 1.0f / (float)FFTN;
    float* ola = g_ola + (size_t)b * LPAD + base;
    #pragma unroll
    for (int h = 0; h < 2; h++) {
        int j = tid + h * 256;
        float val = src[j].x * scale * s_win[j];
        atomicAdd(&ola[j], val);
    }
}

// ---------------- per-batch max |y| ----------------
__global__ void __launch_bounds__(256) k_max() {
    const int b = blockIdx.y;
    const float* ola = g_ola + (size_t)b * LPAD;
    float mx = 0.0f;
    int stride = gridDim.x * blockDim.x;
    for (int i = blockIdx.x * blockDim.x + threadIdx.x; i < LCONST; i += stride) {
        int p = i + PADW;
        float y = ola[p] / g_denom[p];
        mx = fmaxf(mx, fabsf(y));
    }
    __shared__ float red[256];
    red[threadIdx.x] = mx;
    __syncthreads();
    for (int s = 128; s > 0; s >>= 1) {
        if (threadIdx.x < s) red[threadIdx.x] = fmaxf(red[threadIdx.x], red[threadIdx.x + s]);
        __syncthreads();
    }
    if (threadIdx.x == 0)
        atomicMax(&g_maxbits[b], __float_as_uint(red[0]));
}

// ---------------- normalized output ----------------
__global__ void __launch_bounds__(256) k_out(float* __restrict__ out) {
    const int b = blockIdx.y;
    const float* ola = g_ola + (size_t)b * LPAD;
    float* o = out + (size_t)b * LCONST;
    const float inv = 1.0f / (__uint_as_float(g_maxbits[b]) + 1e-8f);
    int stride = gridDim.x * blockDim.x;
    for (int i = blockIdx.x * blockDim.x + threadIdx.x; i < LCONST; i += stride) {
        int p = i + PADW;
        o[i] = (ola[p] / g_denom[p]) * inv;
    }
}

// ---------------- launch ----------------
extern "C" void kernel_launch(void* const* d_in, const int* in_sizes, int n_in,
                              void* d_out, int out_size) {
    const float* mag   = (const float*)d_in[0];   // [32, 80, 2000]
    const float* noise = (const float*)d_in[1];   // [32, 320000]
    float* out = (float*)d_out;                   // [32, 320000]
    (void)in_sizes; (void)n_in; (void)out_size;

    k_init<<<1, 512>>>();
    k_prep<<<2048, 256>>>();
    k_frames<<<dim3(TFR, BATCH), 256>>>(mag, noise);
    k_max<<<dim3(160, BATCH), 256>>>();
    k_out<<<dim3(160, BATCH), 256>>>(out);
}

// round 5
// speedup vs baseline: 2.5026x; 2.5026x over previous
#include <cuda_runtime.h>
#include <math.h>

// ---------------- problem constants ----------------
#define FFTN     512
#define HOPW     128
#define PADW     256
#define NFREQ    257
#define NBANDS   80
#define BATCH    32
#define LCONST   320000
#define NFRAMES  2000
#define TFR      2501                 // STFT frames (L/HOP + 1)
#define LPAD     (LCONST + 2*PADW)    // 320512
#define FPB      2                    // frames per block (64 threads each)

// smem swizzle: pad every 8 float2 -> kills stride-8/64 bank conflicts
#define SW(m) ((m) + ((m) >> 3))     // max 511 -> 574 < 576

// ---------------- device scratch ----------------
__device__ float        g_ola[(size_t)BATCH * LPAD];
__device__ float        g_window[FFTN];
__device__ float2       g_tw512[FFTN];       // W_512^m = e^{-2pi i m/512}
__device__ int          g_band512[FFTN];     // mirrored bin->band+1 (0 = outside bands)
__device__ float        g_rdenom[LPAD];      // 1 / window^2 OLA denominator
__device__ unsigned int g_maxbits[BATCH];

// ---------------- complex helpers ----------------
__device__ __forceinline__ float2 cadd(float2 a, float2 b){ return make_float2(a.x+b.x, a.y+b.y); }
__device__ __forceinline__ float2 csub(float2 a, float2 b){ return make_float2(a.x-b.x, a.y-b.y); }
__device__ __forceinline__ float2 cmul(float2 a, float2 b){
    return make_float2(fmaf(a.x, b.x, -a.y*b.y), fmaf(a.x, b.y, a.y*b.x));
}
// multiply by -i (fwd) / +i (inv)
template<bool INV> __device__ __forceinline__ float2 rot90(float2 a){
    return INV ? make_float2(-a.y, a.x) : make_float2(a.y, -a.x);
}

// 8-point DFT in registers: y_i = sum_j u_j W8^{+-ij}
template<bool INV> __device__ __forceinline__ void bfly8(float2* u){
    const float C = 0.70710678118654752440f;
    // even part: DFT4(u0,u2,u4,u6)
    float2 s0 = cadd(u[0], u[4]), d0 = csub(u[0], u[4]);
    float2 s1 = cadd(u[2], u[6]), d1 = csub(u[2], u[6]);
    float2 E0 = cadd(s0, s1), E2 = csub(s0, s1);
    float2 r1 = rot90<INV>(d1);
    float2 E1 = cadd(d0, r1), E3 = csub(d0, r1);
    // odd part: DFT4(u1,u3,u5,u7)
    float2 t0 = cadd(u[1], u[5]), f0 = csub(u[1], u[5]);
    float2 t1 = cadd(u[3], u[7]), f1 = csub(u[3], u[7]);
    float2 O0 = cadd(t0, t1), O2 = csub(t0, t1);
    float2 r2 = rot90<INV>(f1);
    float2 O1 = cadd(f0, r2), O3 = csub(f0, r2);
    // twiddle odd outputs by W8^{1,2,3} (conjugated when INV)
    O1 = INV ? make_float2(C*(O1.x - O1.y),  C*(O1.x + O1.y))
             : make_float2(C*(O1.x + O1.y),  C*(O1.y - O1.x));
    O2 = rot90<INV>(O2);
    O3 = INV ? make_float2(-C*(O3.x + O3.y), C*(O3.x - O3.y))
             : make_float2( C*(O3.y - O3.x),-C*(O3.x + O3.y));
    u[0] = cadd(E0, O0); u[4] = csub(E0, O0);
    u[1] = cadd(E1, O1); u[5] = csub(E1, O1);
    u[2] = cadd(E2, O2); u[6] = csub(E2, O2);
    u[3] = cadd(E3, O3); u[7] = csub(E3, O3);
}

// middle Stockham radix-8 stage: src -> dst through shared memory
// L = sub-DFT size, TWS = 64/L twiddle stride
template<bool INV> __device__ __forceinline__ void stage_mid(
        const float2* __restrict__ src, float2* __restrict__ dst,
        const float2* __restrict__ s_tw, int lt, int L, int TWS){
    const int k = lt & (L - 1);
    float2 u[8];
    #pragma unroll
    for (int j = 0; j < 8; j++){
        float2 v = src[SW(lt + 64*j)];
        float2 w = s_tw[j * k * TWS];
        if (INV) w.y = -w.y;
        u[j] = cmul(v, w);
    }
    bfly8<INV>(u);
    const int ob = (lt & ~(L - 1)) * 8 + k;
    #pragma unroll
    for (int i = 0; i < 8; i++) dst[SW(ob + i*L)] = u[i];
}

// ---------------- init: tables ----------------
__global__ void k_init(){
    int i = threadIdx.x;   // 512 threads
    double ang = 2.0 * 3.14159265358979323846 * (double)i / (double)FFTN;
    g_window[i] = (float)(0.5 * (1.0 - cos(ang)));
    double a = -2.0 * 3.14159265358979323846 * (double)i / (double)FFTN;
    g_tw512[i] = make_float2((float)cos(a), (float)sin(a));

    // mirrored bin -> band map (+1 encoded, 0 = no band)
    int f = (i <= 256) ? i : (FFTN - i);
    double mel_max = 2595.0 * log10(1.0 + 8000.0 / 700.0);
    double step = mel_max / (double)NBANDS;
    float freq = (float)f / 256.0f;
    int cnt = 0;
    for (int j = 0; j <= NBANDS; j++){
        double mel = (j == NBANDS) ? mel_max : (double)j * step;
        double hz  = 700.0 * (pow(10.0, mel / 2595.0) - 1.0);
        float  e   = (float)(hz / 8000.0);
        if (e <= freq) cnt++;           // searchsorted side='right'
    }
    int band = cnt - 1;
    g_band512[i] = (band >= 0 && band < NBANDS) ? (band + 1) : 0;
    if (i < BATCH) g_maxbits[i] = 0u;
}

// ---------------- prep: zero OLA + reciprocal denominator ----------------
__global__ void k_prep(){
    int stride = gridDim.x * blockDim.x;
    int idx = blockIdx.x * blockDim.x + threadIdx.x;
    float4* z = (float4*)g_ola;
    const size_t n4 = (size_t)BATCH * LPAD / 4;
    for (size_t i = idx; i < n4; i += stride) z[i] = make_float4(0.f, 0.f, 0.f, 0.f);
    for (int p = idx; p < LPAD; p += stride){
        float wsq = 0.0f;
        int tmax = p >> 7;
        #pragma unroll
        for (int dt = 0; dt < 4; dt++){
            int t = tmax - dt;
            if (t >= 0 && t < TFR){
                float w = g_window[p - t * HOPW];
                wsq = fmaf(w, w, wsq);
            }
        }
        g_rdenom[p] = (wsq > 1e-11f) ? (1.0f / wsq) : 1.0f;
    }
}

// ---------------- per-frame STFT -> mask -> ISTFT -> OLA ----------------
__global__ void __launch_bounds__(128)
k_frames(const float* __restrict__ mag, const float* __restrict__ noise){
    __shared__ float2 sbuf[FPB][2][576];
    __shared__ float2 s_tw[FFTN];
    __shared__ float  s_win[FFTN];
    __shared__ int    s_band[FFTN];
    __shared__ float  s_mb[FPB][NBANDS + 1];

    const int tid = threadIdx.x;
    const int fr  = tid >> 6;
    const int lt  = tid & 63;
    const int b   = blockIdx.y;
    const int t0  = blockIdx.x * FPB + fr;
    const int t   = (t0 < TFR) ? t0 : (TFR - 1);

    // stage tables
    #pragma unroll
    for (int h = 0; h < 4; h++){
        int i = tid + h * 128;
        s_tw[i]   = g_tw512[i];
        s_win[i]  = g_window[i];
        s_band[i] = g_band512[i];
    }
    // per-frame interpolated band magnitudes
    {
        double pos = (double)t * ((double)(NFRAMES - 1) / (double)(TFR - 1));
        int i0 = (int)pos;
        int i1 = (i0 + 1 < NFRAMES) ? (i0 + 1) : (NFRAMES - 1);
        float w = (float)(pos - (double)i0);
        const float* mrow = mag + (size_t)b * NBANDS * NFRAMES;
        #pragma unroll
        for (int band = lt; band < NBANDS; band += 64){
            const float* row = mrow + (size_t)band * NFRAMES;
            s_mb[fr][band + 1] = fmaf(row[i1] - row[i0], w, row[i0]);
        }
        if (lt == 0) s_mb[fr][0] = 0.0f;
    }
    __syncthreads();   // (A) tables + masks ready

    float2* buf0 = sbuf[fr][0];
    float2* buf1 = sbuf[fr][1];
    const int base = t * HOPW;
    const float* np = noise + (size_t)b * LCONST;

    // ---- forward stage 1 (l=1, twiddle-free): fused with global load ----
    float2 u[8];
    #pragma unroll
    for (int j = 0; j < 8; j++){
        int idx = lt + 64 * j;
        int q = base + idx - PADW;
        q = (q < 0) ? -q : q;
        q = (q >= LCONST) ? (2 * (LCONST - 1) - q) : q;
        u[j] = make_float2(np[q] * s_win[idx], 0.0f);
    }
    bfly8<false>(u);
    #pragma unroll
    for (int i = 0; i < 8; i++) buf0[SW(8 * lt + i)] = u[i];
    __syncthreads();   // (B)

    // ---- forward stage 2 (l=8) ----
    stage_mid<false>(buf0, buf1, s_tw, lt, 8, 8);
    __syncthreads();   // (C)

    // ---- forward stage 3 (l=64): ends in registers, natural order ----
    {
        const int k = lt;   // L=64 -> k = lt, blk = 0
        #pragma unroll
        for (int j = 0; j < 8; j++){
            float2 v = buf1[SW(lt + 64 * j)];
            float2 w = s_tw[j * k];
            u[j] = cmul(v, w);
        }
        bfly8<false>(u);
        // u[i] = Y[lt + 64*i]
    }

    // ---- mask in registers (Hermitian via mirrored band table) ----
    #pragma unroll
    for (int i = 0; i < 8; i++){
        float m = s_mb[fr][s_band[lt + 64 * i]];
        u[i].x *= m; u[i].y *= m;
    }

    // ---- inverse stage 1 (l=1): input layout == current registers ----
    bfly8<true>(u);
    #pragma unroll
    for (int i = 0; i < 8; i++) buf0[SW(8 * lt + i)] = u[i];
    __syncthreads();   // (D)

    // ---- inverse stage 2 (l=8) ----
    stage_mid<true>(buf0, buf1, s_tw, lt, 8, 8);
    __syncthreads();   // (E)

    // ---- inverse stage 3 (l=64): ends in registers -> window + OLA ----
    {
        const int k = lt;
        #pragma unroll
        for (int j = 0; j < 8; j++){
            float2 v = buf1[SW(lt + 64 * j)];
            float2 w = s_tw[j * k];
            w.y = -w.y;
            u[j] = cmul(v, w);
        }
        bfly8<true>(u);
    }

    if (t0 < TFR){
        const float scale = 1.0f / (float)FFTN;
        float* ola = g_ola + (size_t)b * LPAD + base;
        #pragma unroll
        for (int i = 0; i < 8; i++){
            int idx = lt + 64 * i;
            atomicAdd(&ola[idx], u[i].x * scale * s_win[idx]);
        }
    }
}

// ---------------- per-batch max |y| ----------------
__global__ void __launch_bounds__(256) k_max(){
    const int b = blockIdx.y;
    const float4* ola = (const float4*)(g_ola + (size_t)b * LPAD + PADW);
    const float4* rd  = (const float4*)(g_rdenom + PADW);
    float mx = 0.0f;
    int stride = gridDim.x * blockDim.x;
    for (int i = blockIdx.x * blockDim.x + threadIdx.x; i < LCONST / 4; i += stride){
        float4 a = ola[i]; float4 r = rd[i];
        float m0 = fmaxf(fabsf(a.x * r.x), fabsf(a.y * r.y));
        float m1 = fmaxf(fabsf(a.z * r.z), fabsf(a.w * r.w));
        mx = fmaxf(mx, fmaxf(m0, m1));
    }
    #pragma unroll
    for (int o = 16; o; o >>= 1) mx = fmaxf(mx, __shfl_xor_sync(0xffffffffu, mx, o));
    __shared__ float red[8];
    if ((threadIdx.x & 31) == 0) red[threadIdx.x >> 5] = mx;
    __syncthreads();
    if (threadIdx.x == 0){
        float m2 = red[0];
        #pragma unroll
        for (int w = 1; w < 8; w++) m2 = fmaxf(m2, red[w]);
        atomicMax(&g_maxbits[b], __float_as_uint(m2));
    }
}

// ---------------- normalized output ----------------
__global__ void __launch_bounds__(256) k_out(float* __restrict__ out){
    const int b = blockIdx.y;
    const float4* ola = (const float4*)(g_ola + (size_t)b * LPAD + PADW);
    const float4* rd  = (const float4*)(g_rdenom + PADW);
    float4* o = (float4*)(out + (size_t)b * LCONST);
    const float inv = 1.0f / (__uint_as_float(g_maxbits[b]) + 1e-8f);
    int stride = gridDim.x * blockDim.x;
    for (int i = blockIdx.x * blockDim.x + threadIdx.x; i < LCONST / 4; i += stride){
        float4 a = ola[i]; float4 r = rd[i];
        o[i] = make_float4(a.x * r.x * inv, a.y * r.y * inv,
                           a.z * r.z * inv, a.w * r.w * inv);
    }
}

// ---------------- launch ----------------
extern "C" void kernel_launch(void* const* d_in, const int* in_sizes, int n_in,
                              void* d_out, int out_size) {
    const float* mag   = (const float*)d_in[0];   // [32, 80, 2000]
    const float* noise = (const float*)d_in[1];   // [32, 320000]
    float* out = (float*)d_out;                   // [32, 320000]
    (void)in_sizes; (void)n_in; (void)out_size;

    k_init<<<1, 512>>>();
    k_prep<<<1024, 256>>>();
    k_frames<<<dim3((TFR + FPB - 1) / FPB, BATCH), 128>>>(mag, noise);
    k_max<<<dim3(64, BATCH), 256>>>();
    k_out<<<dim3(64, BATCH), 256>>>(out);
}

// round 7
// speedup vs baseline: 3.2967x; 1.3173x over previous
#include <cuda_runtime.h>
#include <math.h>

// ---------------- problem constants ----------------
#define FFTN     512
#define HOPW     128
#define PADW     256
#define NBANDS   80
#define BATCH    32
#define LCONST   320000
#define NFRAMES  2000
#define TFR      2501                 // STFT frames (L/HOP + 1)
#define LPAD     (LCONST + 2*PADW)    // 320512

// chunked-OLA geometry: 12 frames (6 real-pairs) per block
#define CF       12                   // frames per chunk
#define CH       209                  // ceil(2501/12)
#define LANES    3                    // concurrent pairs (64 threads each)
#define ITERS    2                    // 6 pairs / 3 lanes
#define OWN      (CF*HOPW)            // 1536 owned samples per chunk
#define SPILL    384                  // rightward overlap past owned range
#define SACC     (OWN + SPILL)        // 1920 shared accumulator

// smem swizzle: pad every 8 float2 -> kills stride-8/64 bank conflicts
#define SW(m) ((m) + ((m) >> 3))     // max 511 -> 574 < 576

// ---------------- device scratch ----------------
__device__ float        g_ola[(size_t)BATCH * LPAD];
__device__ float        g_spill[BATCH][CH][SPILL];
__device__ float        g_window[FFTN];
__device__ float2       g_tw512[FFTN];       // W_512^m
__device__ int          g_band512[FFTN];     // mirrored bin->band+1 (0 = outside)
__device__ float        g_rdenom[LPAD];      // 1 / window^2 OLA denominator
__device__ unsigned int g_maxbits[BATCH];

// ---------------- complex helpers ----------------
__device__ __forceinline__ float2 cadd(float2 a, float2 b){ return make_float2(a.x+b.x, a.y+b.y); }
__device__ __forceinline__ float2 csub(float2 a, float2 b){ return make_float2(a.x-b.x, a.y-b.y); }
__device__ __forceinline__ float2 cmul(float2 a, float2 b){
    return make_float2(fmaf(a.x, b.x, -a.y*b.y), fmaf(a.x, b.y, a.y*b.x));
}
template<bool INV> __device__ __forceinline__ float2 rot90(float2 a){
    return INV ? make_float2(-a.y, a.x) : make_float2(a.y, -a.x);
}

// 8-point DFT in registers
template<bool INV> __device__ __forceinline__ void bfly8(float2* u){
    const float C = 0.70710678118654752440f;
    float2 s0 = cadd(u[0], u[4]), d0 = csub(u[0], u[4]);
    float2 s1 = cadd(u[2], u[6]), d1 = csub(u[2], u[6]);
    float2 E0 = cadd(s0, s1), E2 = csub(s0, s1);
    float2 r1 = rot90<INV>(d1);
    float2 E1 = cadd(d0, r1), E3 = csub(d0, r1);
    float2 t0 = cadd(u[1], u[5]), f0 = csub(u[1], u[5]);
    float2 t1 = cadd(u[3], u[7]), f1 = csub(u[3], u[7]);
    float2 O0 = cadd(t0, t1), O2 = csub(t0, t1);
    float2 r2 = rot90<INV>(f1);
    float2 O1 = cadd(f0, r2), O3 = csub(f0, r2);
    O1 = INV ? make_float2(C*(O1.x - O1.y),  C*(O1.x + O1.y))
             : make_float2(C*(O1.x + O1.y),  C*(O1.y - O1.x));
    O2 = rot90<INV>(O2);
    O3 = INV ? make_float2(-C*(O3.x + O3.y), C*(O3.x - O3.y))
             : make_float2( C*(O3.y - O3.x),-C*(O3.x + O3.y));
    u[0] = cadd(E0, O0); u[4] = csub(E0, O0);
    u[1] = cadd(E1, O1); u[5] = csub(E1, O1);
    u[2] = cadd(E2, O2); u[6] = csub(E2, O2);
    u[3] = cadd(E3, O3); u[7] = csub(E3, O3);
}

// middle Stockham radix-8 stage (L=8): src -> dst through shared memory
template<bool INV> __device__ __forceinline__ void stage_mid(
        const float2* __restrict__ src, float2* __restrict__ dst,
        const float2* __restrict__ s_tw, int lt){
    const int k = lt & 7;
    float2 u[8];
    #pragma unroll
    for (int j = 0; j < 8; j++){
        float2 v = src[SW(lt + 64*j)];
        float2 w = s_tw[j * k * 8];
        if (INV) w.y = -w.y;
        u[j] = cmul(v, w);
    }
    bfly8<INV>(u);
    const int ob = (lt & ~7) * 8 + k;
    #pragma unroll
    for (int i = 0; i < 8; i++) dst[SW(ob + i*8)] = u[i];
}

// ---------------- init: tables ----------------
__global__ void k_init(){
    int i = threadIdx.x;   // 512 threads
    double ang = 2.0 * 3.14159265358979323846 * (double)i / (double)FFTN;
    g_window[i] = (float)(0.5 * (1.0 - cos(ang)));
    double a = -2.0 * 3.14159265358979323846 * (double)i / (double)FFTN;
    g_tw512[i] = make_float2((float)cos(a), (float)sin(a));

    int f = (i <= 256) ? i : (FFTN - i);
    double mel_max = 2595.0 * log10(1.0 + 8000.0 / 700.0);
    double step = mel_max / (double)NBANDS;
    float freq = (float)f / 256.0f;
    int cnt = 0;
    for (int j = 0; j <= NBANDS; j++){
        double mel = (j == NBANDS) ? mel_max : (double)j * step;
        double hz  = 700.0 * (pow(10.0, mel / 2595.0) - 1.0);
        float  e   = (float)(hz / 8000.0);
        if (e <= freq) cnt++;           // searchsorted side='right'
    }
    int band = cnt - 1;
    g_band512[i] = (band >= 0 && band < NBANDS) ? (band + 1) : 0;
    if (i < BATCH) g_maxbits[i] = 0u;
}

// ---------------- prep: reciprocal OLA denominator (no zeroing needed) ----------------
__global__ void k_prep(){
    int stride = gridDim.x * blockDim.x;
    for (int p = blockIdx.x * blockDim.x + threadIdx.x; p < LPAD; p += stride){
        float wsq = 0.0f;
        int tmax = p >> 7;
        #pragma unroll
        for (int dt = 0; dt < 4; dt++){
            int t = tmax - dt;
            if (t >= 0 && t < TFR){
                float w = g_window[p - t * HOPW];
                wsq = fmaf(w, w, wsq);
            }
        }
        g_rdenom[p] = (wsq > 1e-11f) ? (1.0f / wsq) : 1.0f;
    }
}

// ---------------- chunked frames: paired real FFT -> mask -> IFFT -> smem OLA ----------------
__global__ void __launch_bounds__(192)
k_frames(const float* __restrict__ mag, const float* __restrict__ noise){
    __shared__ float2 sbuf[LANES][2][576];
    __shared__ float2 s_tw[FFTN];
    __shared__ float  s_mb[LANES][2][NBANDS + 1];
    __shared__ float  sacc[SACC];

    const int tid = threadIdx.x;
    const int fr  = tid / 64;        // lane (pair slot)
    const int lt  = tid % 64;
    const int b   = blockIdx.y;
    const int chunk  = blockIdx.x;
    const int frame0 = chunk * CF;

    for (int i = tid; i < FFTN; i += 192) s_tw[i] = g_tw512[i];
    for (int i = tid; i < SACC; i += 192) sacc[i] = 0.0f;

    float rwin[8]; int rband[8];
    #pragma unroll
    for (int j = 0; j < 8; j++){
        rwin[j]  = g_window[lt + 64*j];
        rband[j] = g_band512[lt + 64*j];
    }

    float2* buf0 = sbuf[fr][0];
    float2* buf1 = sbuf[fr][1];
    const float* np   = noise + (size_t)b * LCONST;
    const float* mrow = mag   + (size_t)b * NBANDS * NFRAMES;

    for (int it = 0; it < ITERS; it++){
        const int p   = it * LANES + fr;       // pair index within chunk
        const int fA  = frame0 + 2*p;
        const int fAc = (fA     < TFR) ? fA     : (TFR-1);
        const int fBc = (fA + 1 < TFR) ? fA + 1 : (TFR-1);
        const bool doA = (fA     < TFR);
        const bool doB = (fA + 1 < TFR);

        // per-pair interpolated band magnitudes (both frames)
        #pragma unroll
        for (int half = 0; half < 2; half++){
            int t = half ? fBc : fAc;
            double pos = (double)t * ((double)(NFRAMES-1)/(double)(TFR-1));
            int i0 = (int)pos;
            int i1 = (i0 + 1 < NFRAMES) ? (i0 + 1) : (NFRAMES - 1);
            float w = (float)(pos - (double)i0);
            for (int band = lt; band < NBANDS; band += 64){
                const float* row = mrow + (size_t)band * NFRAMES;
                s_mb[fr][half][band + 1] = fmaf(row[i1] - row[i0], w, row[i0]);
            }
            if (lt == 0) s_mb[fr][half][0] = 0.0f;
        }
        __syncthreads();   // S0: masks ready; buffers free from prev iter

        // ---- load pair (A->re, B->im) + forward stage 1 ----
        float2 u[8];
        const int baseA = fAc * HOPW, baseB = fBc * HOPW;
        #pragma unroll
        for (int j = 0; j < 8; j++){
            int idx = lt + 64*j;
            int qa = baseA + idx - PADW;
            qa = (qa < 0) ? -qa : qa;
            qa = (qa >= LCONST) ? (2*(LCONST-1) - qa) : qa;
            int qb = baseB + idx - PADW;
            qb = (qb < 0) ? -qb : qb;
            qb = (qb >= LCONST) ? (2*(LCONST-1) - qb) : qb;
            u[j] = make_float2(np[qa] * rwin[j], np[qb] * rwin[j]);
        }
        bfly8<false>(u);
        #pragma unroll
        for (int i = 0; i < 8; i++) buf0[SW(8*lt + i)] = u[i];
        __syncthreads();   // S1

        // ---- forward stage 2 ----
        stage_mid<false>(buf0, buf1, s_tw, lt);
        __syncthreads();   // S2

        // ---- forward stage 3 -> natural-order Z into buf0 ----
        #pragma unroll
        for (int j = 0; j < 8; j++)
            u[j] = cmul(buf1[SW(lt + 64*j)], s_tw[j * lt]);
        bfly8<false>(u);
        #pragma unroll
        for (int i = 0; i < 8; i++) buf0[SW(lt + 64*i)] = u[i];
        __syncthreads();   // S3

        // ---- pair-split + mask + recombine + inverse stage 1 ----
        // Z'(m) = (mA+mB)*Z(m) + (mA-mB)*conj(Z(512-m))   (x1/2 folded into scale)
        #pragma unroll
        for (int j = 0; j < 8; j++){
            int m = lt + 64*j;
            float2 Z  = buf0[SW(m)];
            float2 Zm = buf0[SW((FFTN - m) & (FFTN - 1))];
            float mA = s_mb[fr][0][rband[j]];
            float mB = s_mb[fr][1][rband[j]];
            float sp = mA + mB, sm = mA - mB;
            u[j] = make_float2(fmaf(sp, Z.x,  sm * Zm.x),
                               fmaf(sp, Z.y, -sm * Zm.y));
        }
        bfly8<true>(u);
        #pragma unroll
        for (int i = 0; i < 8; i++) buf1[SW(8*lt + i)] = u[i];
        __syncthreads();   // S4

        // ---- inverse stage 2 ----
        stage_mid<true>(buf1, buf0, s_tw, lt);
        __syncthreads();   // S5

        // ---- inverse stage 3 -> registers; Re->frame A, Im->frame B ----
        #pragma unroll
        for (int j = 0; j < 8; j++){
            float2 w = s_tw[j * lt]; w.y = -w.y;
            u[j] = cmul(buf0[SW(lt + 64*j)], w);
        }
        bfly8<true>(u);

        const float scale = 1.0f / (2.0f * (float)FFTN);   // 1/2 (pair) * 1/N (ifft)
        const int posA = (fA - frame0) * HOPW;
        #pragma unroll
        for (int i = 0; i < 8; i++){
            int idx = lt + 64*i;
            float wv = rwin[i] * scale;
            if (doA) atomicAdd(&sacc[posA + idx],        u[i].x * wv);
            if (doB) atomicAdd(&sacc[posA + HOPW + idx], u[i].y * wv);
        }
    }
    __syncthreads();   // sacc complete

    // ---- write owned range (plain stores) + spill ----
    const bool lastc = (chunk == CH - 1);
    const int own_start = frame0 * HOPW;
    const int own_len   = lastc ? (LPAD - own_start) : OWN;
    float* ola = g_ola + (size_t)b * LPAD + own_start;
    for (int s = tid; s < own_len; s += 192) ola[s] = sacc[s];
    if (!lastc)
        for (int s = tid; s < SPILL; s += 192) g_spill[b][chunk][s] = sacc[OWN + s];
}

// ---------------- per-batch max |y| (ola + spill merge) ----------------
__global__ void __launch_bounds__(256) k_max(){
    const int b = blockIdx.y;
    const float4* ola4 = (const float4*)(g_ola + (size_t)b * LPAD + PADW);
    const float4* rd4  = (const float4*)(g_rdenom + PADW);
    float mx = 0.0f;
    int stride = gridDim.x * blockDim.x;
    for (int i = blockIdx.x * blockDim.x + threadIdx.x; i < LCONST / 4; i += stride){
        int gp = PADW + 4*i;
        int ck = gp / OWN;
        int off = gp - ck * OWN;
        float4 a = ola4[i];
        if (ck > 0 && off < SPILL){
            const float4 s = *(const float4*)&g_spill[b][ck - 1][off];
            a.x += s.x; a.y += s.y; a.z += s.z; a.w += s.w;
        }
        float4 r = rd4[i];
        float m0 = fmaxf(fabsf(a.x * r.x), fabsf(a.y * r.y));
        float m1 = fmaxf(fabsf(a.z * r.z), fabsf(a.w * r.w));
        mx = fmaxf(mx, fmaxf(m0, m1));
    }
    #pragma unroll
    for (int o = 16; o; o >>= 1) mx = fmaxf(mx, __shfl_xor_sync(0xffffffffu, mx, o));
    __shared__ float red[8];
    if ((threadIdx.x & 31) == 0) red[threadIdx.x >> 5] = mx;
    __syncthreads();
    if (threadIdx.x == 0){
        float m2 = red[0];
        #pragma unroll
        for (int w = 1; w < 8; w++) m2 = fmaxf(m2, red[w]);
        atomicMax(&g_maxbits[b], __float_as_uint(m2));
    }
}

// ---------------- normalized output ----------------
__global__ void __launch_bounds__(256) k_out(float* __restrict__ out){
    const int b = blockIdx.y;
    const float4* ola4 = (const float4*)(g_ola + (size_t)b * LPAD + PADW);
    const float4* rd4  = (const float4*)(g_rdenom + PADW);
    float4* o = (float4*)(out + (size_t)b * LCONST);
    const float inv = 1.0f / (__uint_as_float(g_maxbits[b]) + 1e-8f);
    int stride = gridDim.x * blockDim.x;
    for (int i = blockIdx.x * blockDim.x + threadIdx.x; i < LCONST / 4; i += stride){
        int gp = PADW + 4*i;
        int ck = gp / OWN;
        int off = gp - ck * OWN;
        float4 a = ola4[i];
        if (ck > 0 && off < SPILL){
            const float4 s = *(const float4*)&g_spill[b][ck - 1][off];
            a.x += s.x; a.y += s.y; a.z += s.z; a.w += s.w;
        }
        float4 r = rd4[i];
        o[i] = make_float4(a.x * r.x * inv, a.y * r.y * inv,
                           a.z * r.z * inv, a.w * r.w * inv);
    }
}

// ---------------- launch ----------------
extern "C" void kernel_launch(void* const* d_in, const int* in_sizes, int n_in,
                              void* d_out, int out_size) {
    const float* mag   = (const float*)d_in[0];   // [32, 80, 2000]
    const float* noise = (const float*)d_in[1];   // [32, 320000]
    float* out = (float*)d_out;                   // [32, 320000]
    (void)in_sizes; (void)n_in; (void)out_size;

    k_init<<<1, 512>>>();
    k_prep<<<160, 256>>>();
    k_frames<<<dim3(CH, BATCH), 192>>>(mag, noise);
    k_max<<<dim3(64, BATCH), 256>>>();
    k_out<<<dim3(64, BATCH), 256>>>(out);
}

// round 8
// speedup vs baseline: 3.3269x; 1.0092x over previous
#include <cuda_runtime.h>
#include <math.h>

// ---------------- problem constants ----------------
#define FFTN     512
#define HOPW     128
#define PADW     256
#define NBANDS   80
#define BATCH    32
#define LCONST   320000
#define NFRAMES  2000
#define TFR      2501                 // STFT frames (L/HOP + 1)
#define LPAD     (LCONST + 2*PADW)    // 320512

// chunked-OLA geometry: 12 frames (6 real-pairs) per block
#define CF       12                   // frames per chunk
#define CH       209                  // ceil(2501/12)
#define LANES    2                    // concurrent pairs (64 threads each)
#define ITERS    3                    // 6 pairs / 2 lanes
#define NTHR     128
#define OWN      (CF*HOPW)            // 1536 owned samples per chunk
#define SPILL    384                  // rightward overlap past owned range
#define SACC     (OWN + SPILL)        // 1920 samples produced per chunk
#define TWSZ     444                  // twiddle entries actually used (max idx 441)

// smem swizzle: pad every 8 float2 -> kills stride-8/64 bank conflicts
#define SW(m) ((m) + ((m) >> 3))     // max 511 -> 574 < 575

// ---------------- device scratch ----------------
__device__ float        g_ola[(size_t)BATCH * LPAD];
__device__ float        g_spill[BATCH][CH][SPILL];
__device__ float        g_window[FFTN];
__device__ float2       g_tw512[FFTN];       // W_512^m
__device__ int          g_band512[FFTN];     // mirrored bin->band+1 (0 = outside)
__device__ float        g_rdenom[LPAD];      // 1 / window^2 OLA denominator
__device__ unsigned int g_maxbits[BATCH];

// ---------------- complex helpers ----------------
__device__ __forceinline__ float2 cadd(float2 a, float2 b){ return make_float2(a.x+b.x, a.y+b.y); }
__device__ __forceinline__ float2 csub(float2 a, float2 b){ return make_float2(a.x-b.x, a.y-b.y); }
__device__ __forceinline__ float2 cmul(float2 a, float2 b){
    return make_float2(fmaf(a.x, b.x, -a.y*b.y), fmaf(a.x, b.y, a.y*b.x));
}
template<bool INV> __device__ __forceinline__ float2 rot90(float2 a){
    return INV ? make_float2(-a.y, a.x) : make_float2(a.y, -a.x);
}

// 8-point DFT in registers
template<bool INV> __device__ __forceinline__ void bfly8(float2* u){
    const float C = 0.70710678118654752440f;
    float2 s0 = cadd(u[0], u[4]), d0 = csub(u[0], u[4]);
    float2 s1 = cadd(u[2], u[6]), d1 = csub(u[2], u[6]);
    float2 E0 = cadd(s0, s1), E2 = csub(s0, s1);
    float2 r1 = rot90<INV>(d1);
    float2 E1 = cadd(d0, r1), E3 = csub(d0, r1);
    float2 t0 = cadd(u[1], u[5]), f0 = csub(u[1], u[5]);
    float2 t1 = cadd(u[3], u[7]), f1 = csub(u[3], u[7]);
    float2 O0 = cadd(t0, t1), O2 = csub(t0, t1);
    float2 r2 = rot90<INV>(f1);
    float2 O1 = cadd(f0, r2), O3 = csub(f0, r2);
    O1 = INV ? make_float2(C*(O1.x - O1.y),  C*(O1.x + O1.y))
             : make_float2(C*(O1.x + O1.y),  C*(O1.y - O1.x));
    O2 = rot90<INV>(O2);
    O3 = INV ? make_float2(-C*(O3.x + O3.y), C*(O3.x - O3.y))
             : make_float2( C*(O3.y - O3.x),-C*(O3.x + O3.y));
    u[0] = cadd(E0, O0); u[4] = csub(E0, O0);
    u[1] = cadd(E1, O1); u[5] = csub(E1, O1);
    u[2] = cadd(E2, O2); u[6] = csub(E2, O2);
    u[3] = cadd(E3, O3); u[7] = csub(E3, O3);
}

// middle Stockham radix-8 stage (L=8): src -> dst through shared memory
template<bool INV> __device__ __forceinline__ void stage_mid(
        const float2* __restrict__ src, float2* __restrict__ dst,
        const float2* __restrict__ s_tw, int lt){
    const int k = lt & 7;
    float2 u[8];
    #pragma unroll
    for (int j = 0; j < 8; j++){
        float2 v = src[SW(lt + 64*j)];
        float2 w = s_tw[j * k * 8];
        if (INV) w.y = -w.y;
        u[j] = cmul(v, w);
    }
    bfly8<INV>(u);
    const int ob = (lt & ~7) * 8 + k;
    #pragma unroll
    for (int i = 0; i < 8; i++) dst[SW(ob + i*8)] = u[i];
}

// ---------------- init: tables ----------------
__global__ void k_init(){
    int i = threadIdx.x;   // 512 threads
    double ang = 2.0 * 3.14159265358979323846 * (double)i / (double)FFTN;
    g_window[i] = (float)(0.5 * (1.0 - cos(ang)));
    double a = -2.0 * 3.14159265358979323846 * (double)i / (double)FFTN;
    g_tw512[i] = make_float2((float)cos(a), (float)sin(a));

    int f = (i <= 256) ? i : (FFTN - i);
    double mel_max = 2595.0 * log10(1.0 + 8000.0 / 700.0);
    double step = mel_max / (double)NBANDS;
    float freq = (float)f / 256.0f;
    int cnt = 0;
    for (int j = 0; j <= NBANDS; j++){
        double mel = (j == NBANDS) ? mel_max : (double)j * step;
        double hz  = 700.0 * (pow(10.0, mel / 2595.0) - 1.0);
        float  e   = (float)(hz / 8000.0);
        if (e <= freq) cnt++;           // searchsorted side='right'
    }
    int band = cnt - 1;
    g_band512[i] = (band >= 0 && band < NBANDS) ? (band + 1) : 0;
    if (i < BATCH) g_maxbits[i] = 0u;
}

// ---------------- prep: reciprocal OLA denominator ----------------
__global__ void k_prep(){
    int stride = gridDim.x * blockDim.x;
    for (int p = blockIdx.x * blockDim.x + threadIdx.x; p < LPAD; p += stride){
        float wsq = 0.0f;
        int tmax = p >> 7;
        #pragma unroll
        for (int dt = 0; dt < 4; dt++){
            int t = tmax - dt;
            if (t >= 0 && t < TFR){
                float w = g_window[p - t * HOPW];
                wsq = fmaf(w, w, wsq);
            }
        }
        g_rdenom[p] = (wsq > 1e-11f) ? (1.0f / wsq) : 1.0f;
    }
}

// ---------------- chunked frames: paired real FFT -> mask -> IFFT -> yfr -> gather ----------------
__global__ void __launch_bounds__(NTHR)
k_frames(const float* __restrict__ mag, const float* __restrict__ noise){
    __shared__ float2 sbuf[LANES][2][575];           // 18400 B
    __shared__ float2 s_tw[TWSZ];                    //  3552 B
    __shared__ float  s_mb[LANES][2][NBANDS + 1];    //  2592 B
    __shared__ float  yfr[CF][FFTN];                 // 24576 B   total 49120 <= 49152

    const int tid = threadIdx.x;
    const int fr  = tid >> 6;        // lane (pair slot)
    const int lt  = tid & 63;
    const int b   = blockIdx.y;
    const int chunk  = blockIdx.x;
    const int frame0 = chunk * CF;

    for (int i = tid; i < TWSZ; i += NTHR) s_tw[i] = g_tw512[i];

    float rwin[8]; int rband[8];
    #pragma unroll
    for (int j = 0; j < 8; j++){
        rwin[j]  = g_window[lt + 64*j];
        rband[j] = g_band512[lt + 64*j];
    }

    float2* buf0 = sbuf[fr][0];
    float2* buf1 = sbuf[fr][1];
    const float* np   = noise + (size_t)b * LCONST;
    const float* mrow = mag   + (size_t)b * NBANDS * NFRAMES;

    for (int it = 0; it < ITERS; it++){
        const int p   = it * LANES + fr;       // pair index within chunk (0..5)
        const int fA  = frame0 + 2*p;
        const int fAc = (fA     < TFR) ? fA     : (TFR-1);
        const int fBc = (fA + 1 < TFR) ? fA + 1 : (TFR-1);
        const bool doA = (fA     < TFR);
        const bool doB = (fA + 1 < TFR);

        // per-pair interpolated band magnitudes (both frames)
        #pragma unroll
        for (int half = 0; half < 2; half++){
            int t = half ? fBc : fAc;
            double pos = (double)t * ((double)(NFRAMES-1)/(double)(TFR-1));
            int i0 = (int)pos;
            int i1 = (i0 + 1 < NFRAMES) ? (i0 + 1) : (NFRAMES - 1);
            float w = (float)(pos - (double)i0);
            for (int band = lt; band < NBANDS; band += 64){
                const float* row = mrow + (size_t)band * NFRAMES;
                s_mb[fr][half][band + 1] = fmaf(row[i1] - row[i0], w, row[i0]);
            }
            if (lt == 0) s_mb[fr][half][0] = 0.0f;
        }
        __syncthreads();   // S0: masks ready; buffers free from prev iter

        // ---- load pair (A->re, B->im) + forward stage 1 ----
        float2 u[8];
        const int baseA = fAc * HOPW, baseB = fBc * HOPW;
        #pragma unroll
        for (int j = 0; j < 8; j++){
            int idx = lt + 64*j;
            int qa = baseA + idx - PADW;
            qa = (qa < 0) ? -qa : qa;
            qa = (qa >= LCONST) ? (2*(LCONST-1) - qa) : qa;
            int qb = baseB + idx - PADW;
            qb = (qb < 0) ? -qb : qb;
            qb = (qb >= LCONST) ? (2*(LCONST-1) - qb) : qb;
            u[j] = make_float2(np[qa] * rwin[j], np[qb] * rwin[j]);
        }
        bfly8<false>(u);
        #pragma unroll
        for (int i = 0; i < 8; i++) buf0[SW(8*lt + i)] = u[i];
        __syncthreads();   // S1

        // ---- forward stage 2 ----
        stage_mid<false>(buf0, buf1, s_tw, lt);
        __syncthreads();   // S2

        // ---- forward stage 3 -> natural-order Z into buf0 ----
        #pragma unroll
        for (int j = 0; j < 8; j++)
            u[j] = cmul(buf1[SW(lt + 64*j)], s_tw[j * lt]);
        bfly8<false>(u);
        #pragma unroll
        for (int i = 0; i < 8; i++) buf0[SW(lt + 64*i)] = u[i];
        __syncthreads();   // S3

        // ---- pair-split + mask + recombine + inverse stage 1 ----
        // Z'(m) = (mA+mB)*Z(m) + (mA-mB)*conj(Z(512-m))   (x1/2 folded into scale)
        #pragma unroll
        for (int j = 0; j < 8; j++){
            int m = lt + 64*j;
            float2 Z  = buf0[SW(m)];
            float2 Zm = buf0[SW((FFTN - m) & (FFTN - 1))];
            float mA = s_mb[fr][0][rband[j]];
            float mB = s_mb[fr][1][rband[j]];
            float sp = mA + mB, sm = mA - mB;
            u[j] = make_float2(fmaf(sp, Z.x,  sm * Zm.x),
                               fmaf(sp, Z.y, -sm * Zm.y));
        }
        bfly8<true>(u);
        #pragma unroll
        for (int i = 0; i < 8; i++) buf1[SW(8*lt + i)] = u[i];
        __syncthreads();   // S4

        // ---- inverse stage 2 ----
        stage_mid<true>(buf1, buf0, s_tw, lt);
        __syncthreads();   // S5

        // ---- inverse stage 3 -> registers; Re->frame A, Im->frame B ----
        #pragma unroll
        for (int j = 0; j < 8; j++){
            float2 w = s_tw[j * lt]; w.y = -w.y;
            u[j] = cmul(buf0[SW(lt + 64*j)], w);
        }
        bfly8<true>(u);

        // ---- window + per-frame store (plain STS, no atomics) ----
        const float scale = 1.0f / (2.0f * (float)FFTN);   // 1/2 (pair) * 1/N (ifft)
        const int lf = 2*p;                                // local frame index
        #pragma unroll
        for (int i = 0; i < 8; i++){
            int idx = lt + 64*i;
            float wv = rwin[i] * scale;
            yfr[lf    ][idx] = doA ? (u[i].x * wv) : 0.0f;
            yfr[lf + 1][idx] = doB ? (u[i].y * wv) : 0.0f;
        }
    }
    __syncthreads();   // all frames ready

    // ---- gather overlap-add (<=4 frames per sample) + global store ----
    const bool lastc = (chunk == CH - 1);
    const int own_start = frame0 * HOPW;
    const int own_len   = lastc ? (LPAD - own_start) : OWN;
    float* ola = g_ola + (size_t)b * LPAD + own_start;
    for (int s = tid; s < SACC; s += NTHR){
        float acc = 0.0f;
        int t0 = s >> 7;
        #pragma unroll
        for (int dt = 0; dt < 4; dt++){
            int t = t0 - dt;
            if (t >= 0 && t < CF)
                acc += yfr[t][s - (t << 7)];
        }
        if (s < own_len)                 ola[s] = acc;
        else if (!lastc && s >= OWN)     g_spill[b][chunk][s - OWN] = acc;
    }
}

// ---------------- per-batch max |y| (ola + spill merge) ----------------
__global__ void __launch_bounds__(256) k_max(){
    const int b = blockIdx.y;
    const float4* ola4 = (const float4*)(g_ola + (size_t)b * LPAD + PADW);
    const float4* rd4  = (const float4*)(g_rdenom + PADW);
    float mx = 0.0f;
    int stride = gridDim.x * blockDim.x;
    for (int i = blockIdx.x * blockDim.x + threadIdx.x; i < LCONST / 4; i += stride){
        int gp = PADW + 4*i;
        int ck = gp / OWN;
        int off = gp - ck * OWN;
        float4 a = ola4[i];
        if (ck > 0 && off < SPILL){
            const float4 s = *(const float4*)&g_spill[b][ck - 1][off];
            a.x += s.x; a.y += s.y; a.z += s.z; a.w += s.w;
        }
        float4 r = rd4[i];
        float m0 = fmaxf(fabsf(a.x * r.x), fabsf(a.y * r.y));
        float m1 = fmaxf(fabsf(a.z * r.z), fabsf(a.w * r.w));
        mx = fmaxf(mx, fmaxf(m0, m1));
    }
    #pragma unroll
    for (int o = 16; o; o >>= 1) mx = fmaxf(mx, __shfl_xor_sync(0xffffffffu, mx, o));
    __shared__ float red[8];
    if ((threadIdx.x & 31) == 0) red[threadIdx.x >> 5] = mx;
    __syncthreads();
    if (threadIdx.x == 0){
        float m2 = red[0];
        #pragma unroll
        for (int w = 1; w < 8; w++) m2 = fmaxf(m2, red[w]);
        atomicMax(&g_maxbits[b], __float_as_uint(m2));
    }
}

// ---------------- normalized output ----------------
__global__ void __launch_bounds__(256) k_out(float* __restrict__ out){
    const int b = blockIdx.y;
    const float4* ola4 = (const float4*)(g_ola + (size_t)b * LPAD + PADW);
    const float4* rd4  = (const float4*)(g_rdenom + PADW);
    float4* o = (float4*)(out + (size_t)b * LCONST);
    const float inv = 1.0f / (__uint_as_float(g_maxbits[b]) + 1e-8f);
    int stride = gridDim.x * blockDim.x;
    for (int i = blockIdx.x * blockDim.x + threadIdx.x; i < LCONST / 4; i += stride){
        int gp = PADW + 4*i;
        int ck = gp / OWN;
        int off = gp - ck * OWN;
        float4 a = ola4[i];
        if (ck > 0 && off < SPILL){
            const float4 s = *(const float4*)&g_spill[b][ck - 1][off];
            a.x += s.x; a.y += s.y; a.z += s.z; a.w += s.w;
        }
        float4 r = rd4[i];
        o[i] = make_float4(a.x * r.x * inv, a.y * r.y * inv,
                           a.z * r.z * inv, a.w * r.w * inv);
    }
}

// ---------------- launch ----------------
extern "C" void kernel_launch(void* const* d_in, const int* in_sizes, int n_in,
                              void* d_out, int out_size) {
    const float* mag   = (const float*)d_in[0];   // [32, 80, 2000]
    const float* noise = (const float*)d_in[1];   // [32, 320000]
    float* out = (float*)d_out;                   // [32, 320000]
    (void)in_sizes; (void)n_in; (void)out_size;

    k_init<<<1, 512>>>();
    k_prep<<<160, 256>>>();
    k_frames<<<dim3(CH, BATCH), NTHR>>>(mag, noise);
    k_max<<<dim3(64, BATCH), 256>>>();
    k_out<<<dim3(64, BATCH), 256>>>(out);
}

// round 9
// speedup vs baseline: 3.5388x; 1.0637x over previous
#include <cuda_runtime.h>
#include <math.h>

// ---------------- problem constants ----------------
#define FFTN     512
#define HOPW     128
#define PADW     256
#define NBANDS   80
#define BATCH    32
#define LCONST   320000
#define NFRAMES  2000
#define TFR      2501                 // STFT frames (L/HOP + 1)
#define LPAD     (LCONST + 2*PADW)    // 320512

// chunked-OLA geometry: 6 frames (3 real-pairs) per block, one pair per lane
#define CF       6                    // frames per chunk
#define CH       417                  // ceil(2501/6)
#define LANES    3                    // concurrent pairs (64 threads each)
#define NTHR     192
#define OWN      (CF*HOPW)            // 768 owned samples per chunk
#define SPILL    384                  // rightward overlap past owned range
#define SACC     (OWN + SPILL)        // 1152 samples produced per chunk
#define TWSZ     444                  // twiddle entries actually used (max idx 441)

// smem swizzle: pad every 8 float2 -> kills stride-8/64 bank conflicts
#define SW(m) ((m) + ((m) >> 3))     // max 511 -> 574 < 575

// ---------------- device scratch ----------------
__device__ float        g_ola[(size_t)BATCH * LPAD];
__device__ float        g_spill[BATCH][CH][SPILL];
__device__ float        g_window[FFTN];
__device__ float2       g_tw512[FFTN];       // W_512^m
__device__ int          g_band512[FFTN];     // mirrored bin->band+1 (0 = outside)
__device__ float        g_rdenom[LPAD];      // 1 / window^2 OLA denominator
__device__ unsigned int g_maxbits[BATCH];

// ---------------- complex helpers ----------------
__device__ __forceinline__ float2 cadd(float2 a, float2 b){ return make_float2(a.x+b.x, a.y+b.y); }
__device__ __forceinline__ float2 csub(float2 a, float2 b){ return make_float2(a.x-b.x, a.y-b.y); }
__device__ __forceinline__ float2 cmul(float2 a, float2 b){
    return make_float2(fmaf(a.x, b.x, -a.y*b.y), fmaf(a.x, b.y, a.y*b.x));
}
template<bool INV> __device__ __forceinline__ float2 rot90(float2 a){
    return INV ? make_float2(-a.y, a.x) : make_float2(a.y, -a.x);
}

// 8-point DFT in registers
template<bool INV> __device__ __forceinline__ void bfly8(float2* u){
    const float C = 0.70710678118654752440f;
    float2 s0 = cadd(u[0], u[4]), d0 = csub(u[0], u[4]);
    float2 s1 = cadd(u[2], u[6]), d1 = csub(u[2], u[6]);
    float2 E0 = cadd(s0, s1), E2 = csub(s0, s1);
    float2 r1 = rot90<INV>(d1);
    float2 E1 = cadd(d0, r1), E3 = csub(d0, r1);
    float2 t0 = cadd(u[1], u[5]), f0 = csub(u[1], u[5]);
    float2 t1 = cadd(u[3], u[7]), f1 = csub(u[3], u[7]);
    float2 O0 = cadd(t0, t1), O2 = csub(t0, t1);
    float2 r2 = rot90<INV>(f1);
    float2 O1 = cadd(f0, r2), O3 = csub(f0, r2);
    O1 = INV ? make_float2(C*(O1.x - O1.y),  C*(O1.x + O1.y))
             : make_float2(C*(O1.x + O1.y),  C*(O1.y - O1.x));
    O2 = rot90<INV>(O2);
    O3 = INV ? make_float2(-C*(O3.x + O3.y), C*(O3.x - O3.y))
             : make_float2( C*(O3.y - O3.x),-C*(O3.x + O3.y));
    u[0] = cadd(E0, O0); u[4] = csub(E0, O0);
    u[1] = cadd(E1, O1); u[5] = csub(E1, O1);
    u[2] = cadd(E2, O2); u[6] = csub(E2, O2);
    u[3] = cadd(E3, O3); u[7] = csub(E3, O3);
}

// ---------------- init: tables ----------------
__global__ void k_init(){
    int i = threadIdx.x;   // 512 threads
    double ang = 2.0 * 3.14159265358979323846 * (double)i / (double)FFTN;
    g_window[i] = (float)(0.5 * (1.0 - cos(ang)));
    double a = -2.0 * 3.14159265358979323846 * (double)i / (double)FFTN;
    g_tw512[i] = make_float2((float)cos(a), (float)sin(a));

    int f = (i <= 256) ? i : (FFTN - i);
    double mel_max = 2595.0 * log10(1.0 + 8000.0 / 700.0);
    double step = mel_max / (double)NBANDS;
    float freq = (float)f / 256.0f;
    int cnt = 0;
    for (int j = 0; j <= NBANDS; j++){
        double mel = (j == NBANDS) ? mel_max : (double)j * step;
        double hz  = 700.0 * (pow(10.0, mel / 2595.0) - 1.0);
        float  e   = (float)(hz / 8000.0);
        if (e <= freq) cnt++;           // searchsorted side='right'
    }
    int band = cnt - 1;
    g_band512[i] = (band >= 0 && band < NBANDS) ? (band + 1) : 0;
    if (i < BATCH) g_maxbits[i] = 0u;
}

// ---------------- prep: reciprocal OLA denominator ----------------
__global__ void k_prep(){
    int stride = gridDim.x * blockDim.x;
    for (int p = blockIdx.x * blockDim.x + threadIdx.x; p < LPAD; p += stride){
        float wsq = 0.0f;
        int tmax = p >> 7;
        #pragma unroll
        for (int dt = 0; dt < 4; dt++){
            int t = tmax - dt;
            if (t >= 0 && t < TFR){
                float w = g_window[p - t * HOPW];
                wsq = fmaf(w, w, wsq);
            }
        }
        g_rdenom[p] = (wsq > 1e-11f) ? (1.0f / wsq) : 1.0f;
    }
}

// ---------------- chunked frames: paired real FFT -> mask -> IFFT -> yfr -> gather ----------------
__global__ void __launch_bounds__(NTHR, 6)
k_frames(const float* __restrict__ mag, const float* __restrict__ noise){
    __shared__ float2 sbuf[LANES][575];              // 13800 B (single buffer per lane)
    __shared__ float2 s_tw[TWSZ];                    //  3552 B
    __shared__ float  s_mb[LANES][2][NBANDS + 1];    //  1944 B
    __shared__ float  yfr[CF][FFTN];                 // 12288 B   total 31584 B

    const int tid = threadIdx.x;
    const int fr  = tid / 64;        // lane (pair slot) 0..2
    const int lt  = tid % 64;
    const int b   = blockIdx.y;
    const int chunk  = blockIdx.x;
    const int frame0 = chunk * CF;

    for (int i = tid; i < TWSZ; i += NTHR) s_tw[i] = g_tw512[i];

    float rwin[8]; int rband[8];
    #pragma unroll
    for (int j = 0; j < 8; j++){
        rwin[j]  = g_window[lt + 64*j];
        rband[j] = g_band512[lt + 64*j];
    }

    float2* buf = sbuf[fr];
    const float* np   = noise + (size_t)b * LCONST;
    const float* mrow = mag   + (size_t)b * NBANDS * NFRAMES;

    const int fA  = frame0 + 2*fr;
    const int fAc = (fA     < TFR) ? fA     : (TFR-1);
    const int fBc = (fA + 1 < TFR) ? fA + 1 : (TFR-1);
    const bool doA = (fA     < TFR);
    const bool doB = (fA + 1 < TFR);

    // per-pair interpolated band magnitudes (both frames)
    #pragma unroll
    for (int half = 0; half < 2; half++){
        int t = half ? fBc : fAc;
        double pos = (double)t * ((double)(NFRAMES-1)/(double)(TFR-1));
        int i0 = (int)pos;
        int i1 = (i0 + 1 < NFRAMES) ? (i0 + 1) : (NFRAMES - 1);
        float w = (float)(pos - (double)i0);
        for (int band = lt; band < NBANDS; band += 64){
            const float* row = mrow + (size_t)band * NFRAMES;
            s_mb[fr][half][band + 1] = fmaf(row[i1] - row[i0], w, row[i0]);
        }
        if (lt == 0) s_mb[fr][half][0] = 0.0f;
    }

    // ---- load pair (A->re, B->im) + forward stage 1 ----
    float2 u[8];
    const int baseA = fAc * HOPW, baseB = fBc * HOPW;
    #pragma unroll
    for (int j = 0; j < 8; j++){
        int idx = lt + 64*j;
        int qa = baseA + idx - PADW;
        qa = (qa < 0) ? -qa : qa;
        qa = (qa >= LCONST) ? (2*(LCONST-1) - qa) : qa;
        int qb = baseB + idx - PADW;
        qb = (qb < 0) ? -qb : qb;
        qb = (qb >= LCONST) ? (2*(LCONST-1) - qb) : qb;
        u[j] = make_float2(np[qa] * rwin[j], np[qb] * rwin[j]);
    }
    bfly8<false>(u);
    #pragma unroll
    for (int i = 0; i < 8; i++) buf[SW(8*lt + i)] = u[i];
    __syncthreads();   // S1: stage-1 data visible (also covers masks)

    // ---- forward stage 2 (in-place: read, sync, write, sync) ----
    {
        const int k = lt & 7;
        #pragma unroll
        for (int j = 0; j < 8; j++)
            u[j] = cmul(buf[SW(lt + 64*j)], s_tw[j * k * 8]);
        bfly8<false>(u);
        __syncthreads();   // S2: all reads done before overwrite
        const int ob = (lt & ~7) * 8 + k;
        #pragma unroll
        for (int i = 0; i < 8; i++) buf[SW(ob + i*8)] = u[i];
    }
    __syncthreads();   // S3

    // ---- forward stage 3 -> natural-order Z, store to buf ----
    #pragma unroll
    for (int j = 0; j < 8; j++)
        u[j] = cmul(buf[SW(lt + 64*j)], s_tw[j * lt]);
    bfly8<false>(u);
    __syncthreads();   // S4: reads done
    #pragma unroll
    for (int i = 0; i < 8; i++) buf[SW(lt + 64*i)] = u[i];   // Z natural
    __syncthreads();   // S5

    // ---- pair-split + mask + recombine + inverse stage 1 ----
    // Z'(m) = (mA+mB)*Z(m) + (mA-mB)*conj(Z(512-m))   (x1/2 folded into scale)
    // Z(m) for own m is still in u[]; only the mirror comes from smem.
    {
        float2 v[8];
        #pragma unroll
        for (int j = 0; j < 8; j++){
            int m = lt + 64*j;
            float2 Zm = buf[SW((FFTN - m) & (FFTN - 1))];
            float mA = s_mb[fr][0][rband[j]];
            float mB = s_mb[fr][1][rband[j]];
            float sp = mA + mB, sm = mA - mB;
            v[j] = make_float2(fmaf(sp, u[j].x,  sm * Zm.x),
                               fmaf(sp, u[j].y, -sm * Zm.y));
        }
        #pragma unroll
        for (int j = 0; j < 8; j++) u[j] = v[j];
    }
    bfly8<true>(u);
    __syncthreads();   // S6: mirror reads done
    #pragma unroll
    for (int i = 0; i < 8; i++) buf[SW(8*lt + i)] = u[i];
    __syncthreads();   // S7

    // ---- inverse stage 2 ----
    {
        const int k = lt & 7;
        #pragma unroll
        for (int j = 0; j < 8; j++){
            float2 w = s_tw[j * k * 8]; w.y = -w.y;
            u[j] = cmul(buf[SW(lt + 64*j)], w);
        }
        bfly8<true>(u);
        __syncthreads();   // S8
        const int ob = (lt & ~7) * 8 + k;
        #pragma unroll
        for (int i = 0; i < 8; i++) buf[SW(ob + i*8)] = u[i];
    }
    __syncthreads();   // S9

    // ---- inverse stage 3 -> registers; Re->frame A, Im->frame B ----
    #pragma unroll
    for (int j = 0; j < 8; j++){
        float2 w = s_tw[j * lt]; w.y = -w.y;
        u[j] = cmul(buf[SW(lt + 64*j)], w);
    }
    bfly8<true>(u);

    // ---- window + per-frame store (plain STS, no atomics) ----
    const float scale = 1.0f / (2.0f * (float)FFTN);   // 1/2 (pair) * 1/N (ifft)
    const int lf = 2*fr;
    #pragma unroll
    for (int i = 0; i < 8; i++){
        int idx = lt + 64*i;
        float wv = rwin[i] * scale;
        yfr[lf    ][idx] = doA ? (u[i].x * wv) : 0.0f;
        yfr[lf + 1][idx] = doB ? (u[i].y * wv) : 0.0f;
    }
    __syncthreads();   // S10: all frames ready

    // ---- gather overlap-add (<=4 frames per sample) + global store ----
    const bool lastc = (chunk == CH - 1);
    const int own_start = frame0 * HOPW;
    const int own_len   = lastc ? (LPAD - own_start) : OWN;
    float* ola = g_ola + (size_t)b * LPAD + own_start;
    for (int s = tid; s < SACC; s += NTHR){
        float acc = 0.0f;
        int t0 = s >> 7;
        #pragma unroll
        for (int dt = 0; dt < 4; dt++){
            int t = t0 - dt;
            if (t >= 0 && t < CF)
                acc += yfr[t][s - (t << 7)];
        }
        if (s < own_len)                 ola[s] = acc;
        else if (!lastc && s >= OWN)     g_spill[b][chunk][s - OWN] = acc;
    }
}

// ---------------- per-batch max |y| (ola + spill merge) ----------------
__global__ void __launch_bounds__(256) k_max(){
    const int b = blockIdx.y;
    const float4* ola4 = (const float4*)(g_ola + (size_t)b * LPAD + PADW);
    const float4* rd4  = (const float4*)(g_rdenom + PADW);
    float mx = 0.0f;
    int stride = gridDim.x * blockDim.x;
    for (int i = blockIdx.x * blockDim.x + threadIdx.x; i < LCONST / 4; i += stride){
        int gp = PADW + 4*i;
        int ck = gp / OWN;
        int off = gp - ck * OWN;
        float4 a = ola4[i];
        if (ck > 0 && off < SPILL){
            const float4 s = *(const float4*)&g_spill[b][ck - 1][off];
            a.x += s.x; a.y += s.y; a.z += s.z; a.w += s.w;
        }
        float4 r = rd4[i];
        float m0 = fmaxf(fabsf(a.x * r.x), fabsf(a.y * r.y));
        float m1 = fmaxf(fabsf(a.z * r.z), fabsf(a.w * r.w));
        mx = fmaxf(mx, fmaxf(m0, m1));
    }
    #pragma unroll
    for (int o = 16; o; o >>= 1) mx = fmaxf(mx, __shfl_xor_sync(0xffffffffu, mx, o));
    __shared__ float red[8];
    if ((threadIdx.x & 31) == 0) red[threadIdx.x >> 5] = mx;
    __syncthreads();
    if (threadIdx.x == 0){
        float m2 = red[0];
        #pragma unroll
        for (int w = 1; w < 8; w++) m2 = fmaxf(m2, red[w]);
        atomicMax(&g_maxbits[b], __float_as_uint(m2));
    }
}

// ---------------- normalized output ----------------
__global__ void __launch_bounds__(256) k_out(float* __restrict__ out){
    const int b = blockIdx.y;
    const float4* ola4 = (const float4*)(g_ola + (size_t)b * LPAD + PADW);
    const float4* rd4  = (const float4*)(g_rdenom + PADW);
    float4* o = (float4*)(out + (size_t)b * LCONST);
    const float inv = 1.0f / (__uint_as_float(g_maxbits[b]) + 1e-8f);
    int stride = gridDim.x * blockDim.x;
    for (int i = blockIdx.x * blockDim.x + threadIdx.x; i < LCONST / 4; i += stride){
        int gp = PADW + 4*i;
        int ck = gp / OWN;
        int off = gp - ck * OWN;
        float4 a = ola4[i];
        if (ck > 0 && off < SPILL){
            const float4 s = *(const float4*)&g_spill[b][ck - 1][off];
            a.x += s.x; a.y += s.y; a.z += s.z; a.w += s.w;
        }
        float4 r = rd4[i];
        o[i] = make_float4(a.x * r.x * inv, a.y * r.y * inv,
                           a.z * r.z * inv, a.w * r.w * inv);
    }
}

// ---------------- launch ----------------
extern "C" void kernel_launch(void* const* d_in, const int* in_sizes, int n_in,
                              void* d_out, int out_size) {
    const float* mag   = (const float*)d_in[0];   // [32, 80, 2000]
    const float* noise = (const float*)d_in[1];   // [32, 320000]
    float* out = (float*)d_out;                   // [32, 320000]
    (void)in_sizes; (void)n_in; (void)out_size;

    k_init<<<1, 512>>>();
    k_prep<<<160, 256>>>();
    k_frames<<<dim3(CH, BATCH), NTHR>>>(mag, noise);
    k_max<<<dim3(64, BATCH), 256>>>();
    k_out<<<dim3(64, BATCH), 256>>>(out);
}